// round 1
// baseline (speedup 1.0000x reference)
#include <cuda_runtime.h>

#define B_TOT 1024
#define N_TOK 128
#define C_DIM 128
#define H 8
#define HD 16
#define SCALE 0.25f

// scratch (static device arrays; no allocation allowed)
__device__ float g_bias[H * N_TOK * N_TOK];          // 512 KB: bias[h][n][j]
__device__ float g_xo[B_TOT * N_TOK * C_DIM];        // 64 MB: attention output (B,N,C)

// ---------------------------------------------------------------------------
// K1: gather relative-position bias into dense [h][n][j]
// ---------------------------------------------------------------------------
__global__ void bias_kernel(const float* __restrict__ tbl, const int* __restrict__ rel) {
    int t = blockIdx.x * blockDim.x + threadIdx.x;   // n*128 + j
    if (t >= N_TOK * N_TOK) return;
    int idx = rel[t];
#pragma unroll
    for (int h = 0; h < H; h++)
        g_bias[h * (N_TOK * N_TOK) + t] = tbl[idx * H + h];
}

// ---------------------------------------------------------------------------
// K2: per-b fused QKV projection + attention + top-2 weighted V
// smem: sq (q, pitch 128) | skT (k transposed [c][j], pitch 129) | sv ([j][c])
// ---------------------------------------------------------------------------
__global__ __launch_bounds__(512, 1)
void attn_kernel(const float* __restrict__ x, const float* __restrict__ mask,
                 const float* __restrict__ Wq, const float* __restrict__ Wkv) {
    extern __shared__ float sm[];
    float* sq  = sm;                  // 128*128 : x, then q*scale
    float* skT = sm + 16384;          // 128*129 : kT[c*129 + j]
    float* sv  = skT + 128 * 129;     // 128*128 : v[j*128 + c]

    const int b   = blockIdx.x;
    const int tid = threadIdx.x;
    const float* xb = x + b * 16384;

    // ---- stage x into sq ----
    for (int i = tid; i < 16384; i += 512) sq[i] = xb[i];
    __syncthreads();

    const int c  = tid & 127;
    const int n0 = tid >> 7;          // 0..3

    // ---- Phase A: k and v projections ----
    {
        float acck[32], accv[32];
#pragma unroll
        for (int e = 0; e < 32; e++) { acck[e] = 0.f; accv[e] = 0.f; }
        for (int t = 0; t < 128; t += 4) {
            float wk[4], wv[4];
#pragma unroll
            for (int u = 0; u < 4; u++) {
                wk[u] = Wkv[(t + u) * 256 + c];
                wv[u] = Wkv[(t + u) * 256 + 128 + c];
            }
#pragma unroll
            for (int e = 0; e < 32; e++) {
                int n = n0 + 4 * e;
                float4 xv = *reinterpret_cast<const float4*>(&sq[n * 128 + t]);
                acck[e] = fmaf(xv.x, wk[0], fmaf(xv.y, wk[1], fmaf(xv.z, wk[2], fmaf(xv.w, wk[3], acck[e]))));
                accv[e] = fmaf(xv.x, wv[0], fmaf(xv.y, wv[1], fmaf(xv.z, wv[2], fmaf(xv.w, wv[3], accv[e]))));
            }
        }
#pragma unroll
        for (int e = 0; e < 32; e++) {
            int n = n0 + 4 * e;
            skT[c * 129 + n] = acck[e];     // transposed
            sv[n * 128 + c]  = accv[e];
        }
    }

    // ---- Phase A: q projection (x still live in sq) ----
    {
        float accq[32];
#pragma unroll
        for (int e = 0; e < 32; e++) accq[e] = 0.f;
        for (int t = 0; t < 128; t += 4) {
            float wq[4];
#pragma unroll
            for (int u = 0; u < 4; u++) wq[u] = Wq[(t + u) * 128 + c];
#pragma unroll
            for (int e = 0; e < 32; e++) {
                int n = n0 + 4 * e;
                float4 xv = *reinterpret_cast<const float4*>(&sq[n * 128 + t]);
                accq[e] = fmaf(xv.x, wq[0], fmaf(xv.y, wq[1], fmaf(xv.z, wq[2], fmaf(xv.w, wq[3], accq[e]))));
            }
        }
        __syncthreads();   // all x reads done before overwrite
#pragma unroll
        for (int e = 0; e < 32; e++)
            sq[(n0 + 4 * e) * 128 + c] = accq[e] * SCALE;
    }
    __syncthreads();

    // ---- Phase B: attention, 16 warps; warp -> (h = w>>1, 64 n-rows) ----
    const int warp = tid >> 5, lane = tid & 31;
    const int h     = warp >> 1;
    const int nbase = (warp & 1) * 64;
    const int c0    = h * HD;
    const float* biasH = g_bias + h * 16384;
    const float* maskW = mask + (b & 63) * 16384;
    float* xoB = g_xo + b * 16384;

    for (int g = 0; g < 16; g++) {
        const int n = nbase + g * 4;
        float qr[4][16];
#pragma unroll
        for (int r = 0; r < 4; r++)
#pragma unroll
            for (int d = 0; d < 16; d++) qr[r][d] = sq[(n + r) * 128 + c0 + d];

        float m1[4], m2[4], Z[4];
        int   i1[4], i2[4];
#pragma unroll
        for (int r = 0; r < 4; r++) { m1[r] = -1e30f; m2[r] = -1e30f; Z[r] = 0.f; i1[r] = 0; i2[r] = 0; }

#pragma unroll
        for (int jj = 0; jj < 4; jj++) {
            const int j = lane + 32 * jj;
            float kc[16];
#pragma unroll
            for (int d = 0; d < 16; d++) kc[d] = skT[(c0 + d) * 129 + j];
#pragma unroll
            for (int r = 0; r < 4; r++) {
                float s = biasH[(n + r) * 128 + j] + maskW[(n + r) * 128 + j];
#pragma unroll
                for (int d = 0; d < 16; d++) s = fmaf(qr[r][d], kc[d], s);
                if (s > m1[r]) {
                    Z[r] = Z[r] * __expf(m1[r] - s) + 1.f;
                    m2[r] = m1[r]; i2[r] = i1[r];
                    m1[r] = s;     i1[r] = j;
                } else {
                    Z[r] += __expf(s - m1[r]);
                    if (s > m2[r]) { m2[r] = s; i2[r] = j; }
                }
            }
        }

        // warp butterfly reduce (all lanes converge to identical state)
#pragma unroll
        for (int r = 0; r < 4; r++) {
            float a1 = m1[r], a2 = m2[r], az = Z[r];
            int   ai1 = i1[r], ai2 = i2[r];
#pragma unroll
            for (int off = 16; off; off >>= 1) {
                float b1  = __shfl_xor_sync(0xFFFFFFFFu, a1, off);
                float b2  = __shfl_xor_sync(0xFFFFFFFFu, a2, off);
                float bz  = __shfl_xor_sync(0xFFFFFFFFu, az, off);
                int   bi1 = __shfl_xor_sync(0xFFFFFFFFu, ai1, off);
                int   bi2 = __shfl_xor_sync(0xFFFFFFFFu, ai2, off);
                float nm1, nm2; int ni1, ni2;
                if (b1 > a1) {
                    nm1 = b1; ni1 = bi1;
                    if (a1 > b2) { nm2 = a1; ni2 = ai1; } else { nm2 = b2; ni2 = bi2; }
                } else {
                    nm1 = a1; ni1 = ai1;
                    if (b1 > a2) { nm2 = b1; ni2 = bi1; } else { nm2 = a2; ni2 = ai2; }
                }
                az = az * __expf(a1 - nm1) + bz * __expf(b1 - nm1);
                a1 = nm1; a2 = nm2; ai1 = ni1; ai2 = ni2;
            }
            const float inv = 1.f / az;
            const float p1 = inv;
            const float p2 = __expf(a2 - a1) * inv;
            if (lane < 16) {
                float val = p1 * sv[ai1 * 128 + c0 + lane] + p2 * sv[ai2 * 128 + c0 + lane];
                xoB[(n + r) * 128 + c0 + lane] = val;
            }
        }
    }
}

// ---------------------------------------------------------------------------
// K3: output projection  out = xo @ Wproj + bproj
// ---------------------------------------------------------------------------
__global__ __launch_bounds__(512, 2)
void proj_kernel(const float* __restrict__ Wp, const float* __restrict__ bp,
                 float* __restrict__ out) {
    extern __shared__ float sx[];    // 128*128
    const int b = blockIdx.x, tid = threadIdx.x;
    const float* xoB = g_xo + b * 16384;
    for (int i = tid; i < 16384; i += 512) sx[i] = xoB[i];
    __syncthreads();

    const int c  = tid & 127;
    const int n0 = tid >> 7;
    float acc[32];
    const float bias = bp[c];
#pragma unroll
    for (int e = 0; e < 32; e++) acc[e] = bias;
    for (int t = 0; t < 128; t += 4) {
        float w[4];
#pragma unroll
        for (int u = 0; u < 4; u++) w[u] = Wp[(t + u) * 128 + c];
#pragma unroll
        for (int e = 0; e < 32; e++) {
            int n = n0 + 4 * e;
            float4 xv = *reinterpret_cast<const float4*>(&sx[n * 128 + t]);
            acc[e] = fmaf(xv.x, w[0], fmaf(xv.y, w[1], fmaf(xv.z, w[2], fmaf(xv.w, w[3], acc[e]))));
        }
    }
    float* outB = out + b * 16384;
#pragma unroll
    for (int e = 0; e < 32; e++)
        outB[(n0 + 4 * e) * 128 + c] = acc[e];
}

// ---------------------------------------------------------------------------
extern "C" void kernel_launch(void* const* d_in, const int* in_sizes, int n_in,
                              void* d_out, int out_size) {
    const float* x    = (const float*)d_in[0];
    const float* mask = (const float*)d_in[1];
    const float* Wq   = (const float*)d_in[2];
    const float* Wkv  = (const float*)d_in[3];
    const float* Wp   = (const float*)d_in[4];
    const float* bp   = (const float*)d_in[5];
    const float* tbl  = (const float*)d_in[6];
    const int*   rel  = (const int*)d_in[7];
    float* out = (float*)d_out;

    bias_kernel<<<64, 256>>>(tbl, rel);

    const size_t smemA = (size_t)(16384 + 128 * 129 + 16384) * sizeof(float);  // 197120
    cudaFuncSetAttribute(attn_kernel, cudaFuncAttributeMaxDynamicSharedMemorySize, (int)smemA);
    attn_kernel<<<B_TOT, 512, smemA>>>(x, mask, Wq, Wkv);

    cudaFuncSetAttribute(proj_kernel, cudaFuncAttributeMaxDynamicSharedMemorySize, 65536);
    proj_kernel<<<B_TOT, 512, 65536>>>(Wp, bp, out);
}

// round 2
// speedup vs baseline: 1.5500x; 1.5500x over previous
#include <cuda_runtime.h>

#define B_TOT 1024
#define N_TOK 128
#define C_DIM 128
#define H 8
#define HD 16
#define SCALE 0.25f

// scratch (static device arrays; no allocation allowed)
__device__ float g_bias[H * N_TOK * N_TOK];          // 512 KB: bias[h][n][j]
__device__ float g_xo[B_TOT * N_TOK * C_DIM];        // 64 MB: attention output (B,N,C)

// ---------------------------------------------------------------------------
// K1: gather relative-position bias into dense [h][n][j]
// ---------------------------------------------------------------------------
__global__ void bias_kernel(const float* __restrict__ tbl, const int* __restrict__ rel) {
    int t = blockIdx.x * blockDim.x + threadIdx.x;   // n*128 + j
    if (t >= N_TOK * N_TOK) return;
    int idx = rel[t];
#pragma unroll
    for (int h = 0; h < H; h++)
        g_bias[h * (N_TOK * N_TOK) + t] = tbl[idx * H + h];
}

// ---------------------------------------------------------------------------
// K2: per-b fused QKV projection + attention + top-2 weighted V
// smem: sq (q, pitch 128) | skT (k transposed [c][j], pitch 129) | sv ([j][c])
// ---------------------------------------------------------------------------
__global__ __launch_bounds__(512, 1)
void attn_kernel(const float* __restrict__ x, const float* __restrict__ mask,
                 const float* __restrict__ Wq, const float* __restrict__ Wkv) {
    extern __shared__ float sm[];
    float* sq  = sm;                  // 128*128 : x, then q*scale
    float* skT = sm + 16384;          // 128*129 : kT[c*129 + j]
    float* sv  = skT + 128 * 129;     // 128*128 : v[j*128 + c]

    const int b   = blockIdx.x;
    const int tid = threadIdx.x;
    const float* xb = x + b * 16384;

    // ---- stage x into sq ----
    for (int i = tid; i < 16384; i += 512) sq[i] = xb[i];
    __syncthreads();

    const int c  = tid & 127;
    const int n0 = tid >> 7;          // 0..3

    // ---- Phase A: k and v projections ----
    {
        float acck[32], accv[32];
#pragma unroll
        for (int e = 0; e < 32; e++) { acck[e] = 0.f; accv[e] = 0.f; }
        for (int t = 0; t < 128; t += 4) {
            float wk[4], wv[4];
#pragma unroll
            for (int u = 0; u < 4; u++) {
                wk[u] = Wkv[(t + u) * 256 + c];
                wv[u] = Wkv[(t + u) * 256 + 128 + c];
            }
#pragma unroll
            for (int e = 0; e < 32; e++) {
                int n = n0 + 4 * e;
                float4 xv = *reinterpret_cast<const float4*>(&sq[n * 128 + t]);
                acck[e] = fmaf(xv.x, wk[0], fmaf(xv.y, wk[1], fmaf(xv.z, wk[2], fmaf(xv.w, wk[3], acck[e]))));
                accv[e] = fmaf(xv.x, wv[0], fmaf(xv.y, wv[1], fmaf(xv.z, wv[2], fmaf(xv.w, wv[3], accv[e]))));
            }
        }
#pragma unroll
        for (int e = 0; e < 32; e++) {
            int n = n0 + 4 * e;
            skT[c * 129 + n] = acck[e];     // transposed
            sv[n * 128 + c]  = accv[e];
        }
    }

    // ---- Phase A: q projection (x still live in sq) ----
    {
        float accq[32];
#pragma unroll
        for (int e = 0; e < 32; e++) accq[e] = 0.f;
        for (int t = 0; t < 128; t += 4) {
            float wq[4];
#pragma unroll
            for (int u = 0; u < 4; u++) wq[u] = Wq[(t + u) * 128 + c];
#pragma unroll
            for (int e = 0; e < 32; e++) {
                int n = n0 + 4 * e;
                float4 xv = *reinterpret_cast<const float4*>(&sq[n * 128 + t]);
                accq[e] = fmaf(xv.x, wq[0], fmaf(xv.y, wq[1], fmaf(xv.z, wq[2], fmaf(xv.w, wq[3], accq[e]))));
            }
        }
        __syncthreads();   // all x reads done before overwrite
#pragma unroll
        for (int e = 0; e < 32; e++)
            sq[(n0 + 4 * e) * 128 + c] = accq[e] * SCALE;
    }
    __syncthreads();

    // ---- Phase B: attention, 16 warps; warp -> (h = w>>1, 64 n-rows) ----
    const int warp = tid >> 5, lane = tid & 31;
    const int h     = warp >> 1;
    const int nbase = (warp & 1) * 64;
    const int c0    = h * HD;
    const float* biasH = g_bias + h * 16384;
    const float* maskW = mask + (b & 63) * 16384;
    float* xoB = g_xo + b * 16384;

    for (int g = 0; g < 16; g++) {
        const int n = nbase + g * 4;
        float qr[4][16];
#pragma unroll
        for (int r = 0; r < 4; r++)
#pragma unroll
            for (int d = 0; d < 16; d++) qr[r][d] = sq[(n + r) * 128 + c0 + d];

        float m1[4], m2[4], Z[4];
        int   i1[4], i2[4];
#pragma unroll
        for (int r = 0; r < 4; r++) { m1[r] = -1e30f; m2[r] = -1e30f; Z[r] = 0.f; i1[r] = 0; i2[r] = 0; }

#pragma unroll
        for (int jj = 0; jj < 4; jj++) {
            const int j = lane + 32 * jj;
            float kc[16];
#pragma unroll
            for (int d = 0; d < 16; d++) kc[d] = skT[(c0 + d) * 129 + j];
#pragma unroll
            for (int r = 0; r < 4; r++) {
                float s = biasH[(n + r) * 128 + j] + maskW[(n + r) * 128 + j];
#pragma unroll
                for (int d = 0; d < 16; d++) s = fmaf(qr[r][d], kc[d], s);
                if (s > m1[r]) {
                    Z[r] = Z[r] * __expf(m1[r] - s) + 1.f;
                    m2[r] = m1[r]; i2[r] = i1[r];
                    m1[r] = s;     i1[r] = j;
                } else {
                    Z[r] += __expf(s - m1[r]);
                    if (s > m2[r]) { m2[r] = s; i2[r] = j; }
                }
            }
        }

        // warp butterfly reduce (all lanes converge to identical state)
#pragma unroll
        for (int r = 0; r < 4; r++) {
            float a1 = m1[r], a2 = m2[r], az = Z[r];
            int   ai1 = i1[r], ai2 = i2[r];
#pragma unroll
            for (int off = 16; off; off >>= 1) {
                float b1  = __shfl_xor_sync(0xFFFFFFFFu, a1, off);
                float b2  = __shfl_xor_sync(0xFFFFFFFFu, a2, off);
                float bz  = __shfl_xor_sync(0xFFFFFFFFu, az, off);
                int   bi1 = __shfl_xor_sync(0xFFFFFFFFu, ai1, off);
                int   bi2 = __shfl_xor_sync(0xFFFFFFFFu, ai2, off);
                float nm1, nm2; int ni1, ni2;
                if (b1 > a1) {
                    nm1 = b1; ni1 = bi1;
                    if (a1 > b2) { nm2 = a1; ni2 = ai1; } else { nm2 = b2; ni2 = bi2; }
                } else {
                    nm1 = a1; ni1 = ai1;
                    if (b1 > a2) { nm2 = b1; ni2 = bi1; } else { nm2 = a2; ni2 = ai2; }
                }
                az = az * __expf(a1 - nm1) + bz * __expf(b1 - nm1);
                a1 = nm1; a2 = nm2; ai1 = ni1; ai2 = ni2;
            }
            const float inv = 1.f / az;
            const float p1 = inv;
            const float p2 = __expf(a2 - a1) * inv;
            if (lane < 16) {
                float val = p1 * sv[ai1 * 128 + c0 + lane] + p2 * sv[ai2 * 128 + c0 + lane];
                xoB[(n + r) * 128 + c0 + lane] = val;
            }
        }
    }
}

// ---------------------------------------------------------------------------
// K3: output projection  out = xo @ Wproj + bproj
// ---------------------------------------------------------------------------
__global__ __launch_bounds__(512, 2)
void proj_kernel(const float* __restrict__ Wp, const float* __restrict__ bp,
                 float* __restrict__ out) {
    extern __shared__ float sx[];    // 128*128
    const int b = blockIdx.x, tid = threadIdx.x;
    const float* xoB = g_xo + b * 16384;
    for (int i = tid; i < 16384; i += 512) sx[i] = xoB[i];
    __syncthreads();

    const int c  = tid & 127;
    const int n0 = tid >> 7;
    float acc[32];
    const float bias = bp[c];
#pragma unroll
    for (int e = 0; e < 32; e++) acc[e] = bias;
    for (int t = 0; t < 128; t += 4) {
        float w[4];
#pragma unroll
        for (int u = 0; u < 4; u++) w[u] = Wp[(t + u) * 128 + c];
#pragma unroll
        for (int e = 0; e < 32; e++) {
            int n = n0 + 4 * e;
            float4 xv = *reinterpret_cast<const float4*>(&sx[n * 128 + t]);
            acc[e] = fmaf(xv.x, w[0], fmaf(xv.y, w[1], fmaf(xv.z, w[2], fmaf(xv.w, w[3], acc[e]))));
        }
    }
    float* outB = out + b * 16384;
#pragma unroll
    for (int e = 0; e < 32; e++)
        outB[(n0 + 4 * e) * 128 + c] = acc[e];
}

// ---------------------------------------------------------------------------
extern "C" void kernel_launch(void* const* d_in, const int* in_sizes, int n_in,
                              void* d_out, int out_size) {
    const float* x    = (const float*)d_in[0];
    const float* mask = (const float*)d_in[1];
    const float* Wq   = (const float*)d_in[2];
    const float* Wkv  = (const float*)d_in[3];
    const float* Wp   = (const float*)d_in[4];
    const float* bp   = (const float*)d_in[5];
    const float* tbl  = (const float*)d_in[6];
    const int*   rel  = (const int*)d_in[7];
    float* out = (float*)d_out;

    bias_kernel<<<64, 256>>>(tbl, rel);

    const size_t smemA = (size_t)(16384 + 128 * 129 + 16384) * sizeof(float);  // 197120
    cudaFuncSetAttribute(attn_kernel, cudaFuncAttributeMaxDynamicSharedMemorySize, (int)smemA);
    attn_kernel<<<B_TOT, 512, smemA>>>(x, mask, Wq, Wkv);

    cudaFuncSetAttribute(proj_kernel, cudaFuncAttributeMaxDynamicSharedMemorySize, 65536);
    proj_kernel<<<B_TOT, 512, 65536>>>(Wp, bp, out);
}

// round 7
// speedup vs baseline: 2.8154x; 1.8164x over previous
#include <cuda_runtime.h>
#include <cuda_bf16.h>
#include <cstdint>

#define B_TOT 1024
#define NW 64

__device__ float g_bm[NW * 8 * 128 * 128];      // bias+mask [w][h][n][j]  (32MB)
__device__ float g_xo[B_TOT * 128 * 128];       // attn output fp32 (64MB)
// packed weight fragments: [tile][ks][lane] -> {pair kp, pair kp+4}
__device__ uint2 g_Pc_h[48 * 8 * 32];           // qkv combined W^T, 3-way split
__device__ uint2 g_Pc_m[48 * 8 * 32];
__device__ uint2 g_Pc_l[48 * 8 * 32];
__device__ uint2 g_Pp_h[16 * 8 * 32];           // proj W^T, 2-way split
__device__ uint2 g_Pp_m[16 * 8 * 32];

__device__ __forceinline__ unsigned short bfb(__nv_bfloat16 h) { return *reinterpret_cast<unsigned short*>(&h); }

__device__ __forceinline__ void split3s(float v, unsigned short& h, unsigned short& m, unsigned short& l) {
    __nv_bfloat16 bh = __float2bfloat16(v);
    float r1 = v - __bfloat162float(bh);
    __nv_bfloat16 bm = __float2bfloat16(r1);
    float r2 = r1 - __bfloat162float(bm);
    h = bfb(bh); m = bfb(bm); l = bfb(__float2bfloat16(r2));
}

__device__ __forceinline__ void hmma(float* d, const uint32_t* a, const uint32_t* b) {
    asm volatile("mma.sync.aligned.m16n8k16.row.col.f32.bf16.bf16.f32 "
                 "{%0,%1,%2,%3},{%4,%5,%6,%7},{%8,%9},{%0,%1,%2,%3};"
                 : "+f"(d[0]), "+f"(d[1]), "+f"(d[2]), "+f"(d[3])
                 : "r"(a[0]), "r"(a[1]), "r"(a[2]), "r"(a[3]), "r"(b[0]), "r"(b[1]));
}

// ---------------- prep ----------------
__global__ void prep_bm(const float* __restrict__ mask, const float* __restrict__ tbl,
                        const int* __restrict__ rel) {
    int t = blockIdx.x * blockDim.x + threadIdx.x;
    if (t >= NW * 16384) return;
    int w = t >> 14, nj = t & 16383;
    int r = rel[nj];
    float mk = mask[t];
#pragma unroll
    for (int h = 0; h < 8; h++)
        g_bm[(((w << 3) + h) << 14) + nj] = tbl[r * 8 + h] + mk;
}

__global__ void prep_w(const float* __restrict__ Wq, const float* __restrict__ Wkv,
                       const float* __restrict__ Wp) {
    int t = blockIdx.x * blockDim.x + threadIdx.x;   // < 16384
    int lane = t & 31, rest = t >> 5;
    int ks = rest & 7, tile = rest >> 3;
    int lr = lane >> 2, lc = lane & 3;
    int kb = ks * 16 + lc * 2;
    int kk[4] = { kb, kb + 1, kb + 8, kb + 9 };
    if (tile < 48) {
        int n = tile * 8 + lr;
        unsigned short h[4], m[4], l[4];
#pragma unroll
        for (int i = 0; i < 4; i++) {
            int k = kk[i];
            float v = (n < 128) ? Wq[k * 128 + n] * 0.25f : Wkv[k * 256 + (n - 128)];
            split3s(v, h[i], m[i], l[i]);
        }
        int idx = (tile * 8 + ks) * 32 + lane;
        g_Pc_h[idx] = make_uint2((uint32_t)h[0] | ((uint32_t)h[1] << 16),
                                 (uint32_t)h[2] | ((uint32_t)h[3] << 16));
        g_Pc_m[idx] = make_uint2((uint32_t)m[0] | ((uint32_t)m[1] << 16),
                                 (uint32_t)m[2] | ((uint32_t)m[3] << 16));
        g_Pc_l[idx] = make_uint2((uint32_t)l[0] | ((uint32_t)l[1] << 16),
                                 (uint32_t)l[2] | ((uint32_t)l[3] << 16));
    } else if (tile < 64) {
        int n = (tile - 48) * 8 + lr;
        unsigned short h[4], m[4], l[4];
#pragma unroll
        for (int i = 0; i < 4; i++)
            split3s(Wp[kk[i] * 128 + n], h[i], m[i], l[i]);
        int idx = ((tile - 48) * 8 + ks) * 32 + lane;
        g_Pp_h[idx] = make_uint2((uint32_t)h[0] | ((uint32_t)h[1] << 16),
                                 (uint32_t)h[2] | ((uint32_t)h[3] << 16));
        g_Pp_m[idx] = make_uint2((uint32_t)m[0] | ((uint32_t)m[1] << 16),
                                 (uint32_t)m[2] | ((uint32_t)m[3] << 16));
    }
}

// ---------------- fused attention ----------------
// smem bytes: XH@0 XM@32768 XL@65536 (u32[128][64], swizzled)
//             K@98304 (f32 pitch130, 66560B)  V@164864 (same)   total 231424
// Q overlays X region after phase A (f32 pitch132, 67584B)
#define SM_XM 32768
#define SM_XL 65536
#define SM_K  98304
#define SM_V  164864
#define ATTN_SMEM 231424
#define PQ 132
#define PK 130
#define PV 130

__global__ __launch_bounds__(512, 1)
void attn_kernel(const float* __restrict__ x) {
    extern __shared__ char sm[];
    uint32_t* XH = reinterpret_cast<uint32_t*>(sm);
    uint32_t* XM = reinterpret_cast<uint32_t*>(sm + SM_XM);
    uint32_t* XL = reinterpret_cast<uint32_t*>(sm + SM_XL);
    float* sQ = reinterpret_cast<float*>(sm);
    float* sK = reinterpret_cast<float*>(sm + SM_K);
    float* sV = reinterpret_cast<float*>(sm + SM_V);

    const int b = blockIdx.x, tid = threadIdx.x;
    const int wid = tid >> 5, lane = tid & 31;

    // stage x -> 3-way bf16 split, swizzled pitch 64
    const float* xb = x + b * 16384;
    for (int p = tid; p < 8192; p += 512) {
        int row = p >> 6, kp = p & 63;
        float2 v = *reinterpret_cast<const float2*>(xb + row * 128 + kp * 2);
        unsigned short h0, m0, l0, h1, m1, l1;
        split3s(v.x, h0, m0, l0);
        split3s(v.y, h1, m1, l1);
        int idx = row * 64 + (kp ^ ((row & 7) << 2));
        XH[idx] = (uint32_t)h0 | ((uint32_t)h1 << 16);
        XM[idx] = (uint32_t)m0 | ((uint32_t)m1 << 16);
        XL[idx] = (uint32_t)l0 | ((uint32_t)l1 << 16);
    }
    __syncthreads();

    // ---- phase A: QKV GEMM via HMMA ----
    const int mt = wid & 7, np = wid >> 3, lr = lane >> 2, lc = lane & 3;
    const int sw = lr << 2;
    const int r0 = (mt * 16 + lr) * 64;
    const int r1 = r0 + 8 * 64;
    float CQ[8][4];

#pragma unroll
    for (int grp = 0; grp < 3; grp++) {
        const int ibase = (grp == 0) ? 8 : (grp == 1) ? 16 : 0;   // K, V, Q
        float C[8][4];
#pragma unroll
        for (int t = 0; t < 8; t++) { C[t][0] = C[t][1] = C[t][2] = C[t][3] = 0.f; }
#pragma unroll 2
        for (int ks = 0; ks < 8; ks++) {
            const int k0 = (ks * 8 + lc) ^ sw;
            const int k1 = (ks * 8 + lc + 4) ^ sw;
            uint32_t ah[4], am[4], al[4];
            ah[0] = XH[r0 + k0]; ah[1] = XH[r1 + k0]; ah[2] = XH[r0 + k1]; ah[3] = XH[r1 + k1];
            am[0] = XM[r0 + k0]; am[1] = XM[r1 + k0]; am[2] = XM[r0 + k1]; am[3] = XM[r1 + k1];
            if (grp != 1) {
                al[0] = XL[r0 + k0]; al[1] = XL[r1 + k0]; al[2] = XL[r0 + k1]; al[3] = XL[r1 + k1];
            }
#pragma unroll
            for (int t = 0; t < 8; t++) {
                const int tile = np + 2 * (ibase + t);
                const int fi = (tile * 8 + ks) * 32 + lane;
                uint2 h2 = __ldg(&g_Pc_h[fi]);
                uint2 m2 = __ldg(&g_Pc_m[fi]);
                uint32_t bh[2] = { h2.x, h2.y };
                uint32_t bm[2] = { m2.x, m2.y };
                hmma(C[t], ah, bh);
                hmma(C[t], ah, bm);
                hmma(C[t], am, bh);
                if (grp != 1) {
                    uint2 l2 = __ldg(&g_Pc_l[fi]);
                    uint32_t bl[2] = { l2.x, l2.y };
                    hmma(C[t], am, bm);
                    hmma(C[t], ah, bl);
                    hmma(C[t], al, bh);
                }
            }
        }
        if (grp == 2) {
#pragma unroll
            for (int t = 0; t < 8; t++) {
                CQ[t][0] = C[t][0]; CQ[t][1] = C[t][1];
                CQ[t][2] = C[t][2]; CQ[t][3] = C[t][3];
            }
        } else {
            float* dst = (grp == 0) ? sK : sV;
            const int pitch = (grp == 0) ? PK : PV;
            const int coff = (grp == 0) ? 128 : 256;
#pragma unroll
            for (int t = 0; t < 8; t++) {
                const int col = (np + 2 * (ibase + t)) * 8 + lc * 2 - coff;
                const int row = mt * 16 + lr;
                *reinterpret_cast<float2*>(dst + row * pitch + col) = make_float2(C[t][0], C[t][1]);
                *reinterpret_cast<float2*>(dst + (row + 8) * pitch + col) = make_float2(C[t][2], C[t][3]);
            }
        }
    }
    __syncthreads();     // all x reads complete before Q overlays X
#pragma unroll
    for (int t = 0; t < 8; t++) {
        const int col = (np + 2 * t) * 8 + lc * 2;
        const int row = mt * 16 + lr;
        *reinterpret_cast<float2*>(sQ + row * PQ + col) = make_float2(CQ[t][0], CQ[t][1]);
        *reinterpret_cast<float2*>(sQ + (row + 8) * PQ + col) = make_float2(CQ[t][2], CQ[t][3]);
    }
    __syncthreads();

    // ---- phase B: logits + branchless top-2 + softmax weights ----
    const int h = wid >> 1, c0 = h * 16, nb = (wid & 1) * 64;
    const float* bmh = g_bm + ((((b & 63) << 3) + h) << 14);
    float* xoB = g_xo + (b << 14);

    for (int g = 0; g < 32; g++) {
        const int n = nb + g * 2;
        float4 qa[2][4];
#pragma unroll
        for (int r = 0; r < 2; r++)
#pragma unroll
            for (int u = 0; u < 4; u++)
                qa[r][u] = *reinterpret_cast<const float4*>(&sQ[(n + r) * PQ + c0 + u * 4]);

        float sc[2][4];
        float m1[2] = { -3e38f, -3e38f }, m2[2] = { -3e38f, -3e38f };
        int i1[2] = { 0, 0 }, i2[2] = { 0, 0 };
#pragma unroll
        for (int jj = 0; jj < 4; jj++) {
            const int j = jj * 32 + lane;
            const float2* kr = reinterpret_cast<const float2*>(sK + j * PK + c0);
            float2 k0 = kr[0], k1 = kr[1], k2 = kr[2], k3 = kr[3];
            float2 k4 = kr[4], k5 = kr[5], k6 = kr[6], k7 = kr[7];
#pragma unroll
            for (int r = 0; r < 2; r++) {
                float s = bmh[((n + r) << 7) + j];
                s = fmaf(qa[r][0].x, k0.x, s); s = fmaf(qa[r][0].y, k0.y, s);
                s = fmaf(qa[r][0].z, k1.x, s); s = fmaf(qa[r][0].w, k1.y, s);
                s = fmaf(qa[r][1].x, k2.x, s); s = fmaf(qa[r][1].y, k2.y, s);
                s = fmaf(qa[r][1].z, k3.x, s); s = fmaf(qa[r][1].w, k3.y, s);
                s = fmaf(qa[r][2].x, k4.x, s); s = fmaf(qa[r][2].y, k4.y, s);
                s = fmaf(qa[r][2].z, k5.x, s); s = fmaf(qa[r][2].w, k5.y, s);
                s = fmaf(qa[r][3].x, k6.x, s); s = fmaf(qa[r][3].y, k6.y, s);
                s = fmaf(qa[r][3].z, k7.x, s); s = fmaf(qa[r][3].w, k7.y, s);
                sc[r][jj] = s;
                bool g1 = s > m1[r], g2 = s > m2[r];
                float om1 = m1[r]; int oi1 = i1[r];
                m2[r] = g1 ? om1 : (g2 ? s : m2[r]);
                i2[r] = g1 ? oi1 : (g2 ? j : i2[r]);
                m1[r] = g1 ? s : om1;
                i1[r] = g1 ? j : oi1;
            }
        }
#pragma unroll
        for (int r = 0; r < 2; r++) {
            float a1 = m1[r], a2 = m2[r];
            int ai1 = i1[r], ai2 = i2[r];
#pragma unroll
            for (int off = 16; off; off >>= 1) {
                float b1 = __shfl_xor_sync(0xFFFFFFFFu, a1, off);
                int  bi1 = __shfl_xor_sync(0xFFFFFFFFu, ai1, off);
                float b2 = __shfl_xor_sync(0xFFFFFFFFu, a2, off);
                int  bi2 = __shfl_xor_sync(0xFFFFFFFFu, ai2, off);
                bool agt = (a1 > b1) || (a1 == b1 && ai1 < bi1);
                float w2 = agt ? a2 : b2; int wi2 = agt ? ai2 : bi2;
                float l1 = agt ? b1 : a1; int li1 = agt ? bi1 : ai1;
                a1 = agt ? a1 : b1; ai1 = agt ? ai1 : bi1;
                bool s2 = (w2 > l1) || (w2 == l1 && wi2 < li1);
                a2 = s2 ? w2 : l1; ai2 = s2 ? wi2 : li1;
            }
            float z = __expf(sc[r][0] - a1) + __expf(sc[r][1] - a1)
                    + __expf(sc[r][2] - a1) + __expf(sc[r][3] - a1);
#pragma unroll
            for (int off = 16; off; off >>= 1)
                z += __shfl_xor_sync(0xFFFFFFFFu, z, off);
            float inv = 1.0f / z;
            float p2 = __expf(a2 - a1) * inv;
            if (lane < 16) {
                float val = fmaf(inv, sV[ai1 * PV + c0 + lane], p2 * sV[ai2 * PV + c0 + lane]);
                xoB[((n + r) << 7) + c0 + lane] = val;
            }
        }
    }
}

// ---------------- output projection (HMMA, 2-way split, 3 products) ----------------
#define PPX 68
#define PROJ_XL 34816
#define PROJ_SMEM 69632

__global__ __launch_bounds__(512, 2)
void proj_kernel(const float* __restrict__ bp, float* __restrict__ out) {
    extern __shared__ char sm[];
    uint32_t* XH = reinterpret_cast<uint32_t*>(sm);
    uint32_t* XL = reinterpret_cast<uint32_t*>(sm + PROJ_XL);
    const int b = blockIdx.x, tid = threadIdx.x;
    const int wid = tid >> 5, lane = tid & 31;

    const float* xb = g_xo + (b << 14);
    for (int p = tid; p < 8192; p += 512) {
        int row = p >> 6, kp = p & 63;
        float2 v = *reinterpret_cast<const float2*>(xb + row * 128 + kp * 2);
        unsigned short h0, m0, l0, h1, m1, l1;
        split3s(v.x, h0, m0, l0);
        split3s(v.y, h1, m1, l1);
        XH[row * PPX + kp] = (uint32_t)h0 | ((uint32_t)h1 << 16);
        XL[row * PPX + kp] = (uint32_t)m0 | ((uint32_t)m1 << 16);
    }
    __syncthreads();

    const int mt = wid & 7, np = wid >> 3, lr = lane >> 2, lc = lane & 3;
    const int arow = (mt * 16 + lr) * PPX;

    float C[8][4];
#pragma unroll
    for (int t = 0; t < 8; t++) { C[t][0] = C[t][1] = C[t][2] = C[t][3] = 0.f; }
#pragma unroll 2
    for (int ks = 0; ks < 8; ks++) {
        const int ai = arow + ks * 8 + lc;
        uint32_t ah[4], al[4];
        ah[0] = XH[ai];     ah[1] = XH[ai + 8 * PPX];
        ah[2] = XH[ai + 4]; ah[3] = XH[ai + 8 * PPX + 4];
        al[0] = XL[ai];     al[1] = XL[ai + 8 * PPX];
        al[2] = XL[ai + 4]; al[3] = XL[ai + 8 * PPX + 4];
#pragma unroll
        for (int t = 0; t < 8; t++) {
            const int tile = np + 2 * t;
            const int fi = (tile * 8 + ks) * 32 + lane;
            uint2 h2 = __ldg(&g_Pp_h[fi]);
            uint2 m2 = __ldg(&g_Pp_m[fi]);
            uint32_t bh[2] = { h2.x, h2.y };
            uint32_t bm[2] = { m2.x, m2.y };
            hmma(C[t], ah, bh);
            hmma(C[t], ah, bm);
            hmma(C[t], al, bh);
        }
    }
    float* outB = out + (b << 14);
#pragma unroll
    for (int t = 0; t < 8; t++) {
        const int col = (np + 2 * t) * 8 + lc * 2;
        const int row = mt * 16 + lr;
        const float b0 = __ldg(bp + col), b1 = __ldg(bp + col + 1);
        *reinterpret_cast<float2*>(outB + row * 128 + col) = make_float2(C[t][0] + b0, C[t][1] + b1);
        *reinterpret_cast<float2*>(outB + (row + 8) * 128 + col) = make_float2(C[t][2] + b0, C[t][3] + b1);
    }
}

// ---------------------------------------------------------------------------
extern "C" void kernel_launch(void* const* d_in, const int* in_sizes, int n_in,
                              void* d_out, int out_size) {
    const float* x    = (const float*)d_in[0];
    const float* mask = (const float*)d_in[1];
    const float* Wq   = (const float*)d_in[2];
    const float* Wkv  = (const float*)d_in[3];
    const float* Wp   = (const float*)d_in[4];
    const float* bp   = (const float*)d_in[5];
    const float* tbl  = (const float*)d_in[6];
    const int*   rel  = (const int*)d_in[7];
    float* out = (float*)d_out;

    prep_w<<<32, 512>>>(Wq, Wkv, Wp);
    prep_bm<<<2048, 512>>>(mask, tbl, rel);

    cudaFuncSetAttribute(attn_kernel, cudaFuncAttributeMaxDynamicSharedMemorySize, ATTN_SMEM);
    attn_kernel<<<B_TOT, 512, ATTN_SMEM>>>(x);

    cudaFuncSetAttribute(proj_kernel, cudaFuncAttributeMaxDynamicSharedMemorySize, PROJ_SMEM);
    proj_kernel<<<B_TOT, 512, PROJ_SMEM>>>(bp, out);
}